// round 3
// baseline (speedup 1.0000x reference)
#include <cuda_runtime.h>
#include <math.h>

// FourierBlock: out = irfft2(modemix(rfft2(x))) + MLP(x) + Conv3x3(x)
// B=8, C=64, H=W=256, modes: kh in {0..31}u{224..255} (64), kw in {0..31}

// ----------------------------- scratch ------------------------------------
__device__ __align__(16) float2 g_Y1[512*256*32]; // [bc][h][kw]
__device__ __align__(16) float2 g_Y2[512*64*32];  // [bc][khi][kw]
__device__ __align__(16) float2 g_Z [512*64*32];  // [bco][khi][kw]
__device__ __align__(16) float2 g_G [512*256*32]; // [bco][h][kw]
__device__ __align__(16) float2 g_TwA[256*32];    // [w][kw]  (cos,-sin)
__device__ __align__(16) float2 g_TwB[256*64];    // [h][khi] (cos,-sin)
__device__ __align__(16) float2 g_TwC[64*256];    // [khi][h] (cos,+sin)
__device__ __align__(16) float  g_Ct[32*256];     // [kw][w] coef*cos/65536
__device__ __align__(16) float  g_St[32*256];     // [kw][w] -coef*sin/65536
__device__ __align__(16) float2 g_Wp[2048*4096];  // [mode][ci*64+co]
__device__ __align__(16) float  g_Wc[64*9*64];    // [ci][tap][co]
__device__ __align__(16) float  g_W1t[64*128];    // [ci][hid]
__device__ __align__(16) float  g_W2t[128*64];    // [hid][co]

// ----------------------------- tables --------------------------------------
__global__ void k_tables() {
    int idx = blockIdx.x * 256 + threadIdx.x; // < 16384
    float s, c;
    if (idx < 256*32) { // TwA
        int w = idx >> 5, kw = idx & 31;
        sincospif((float)((w*kw)&255) * (1.0f/128.0f), &s, &c);
        g_TwA[idx] = make_float2(c, -s);
    }
    if (idx < 256*64) { // TwB
        int h = idx >> 6, khi = idx & 63;
        int kh = (khi < 32) ? khi : khi + 192;
        sincospif((float)((h*kh)&255) * (1.0f/128.0f), &s, &c);
        g_TwB[idx] = make_float2(c, -s);
    }
    if (idx < 64*256) { // TwC
        int khi = idx >> 8, h = idx & 255;
        int kh = (khi < 32) ? khi : khi + 192;
        sincospif((float)((h*kh)&255) * (1.0f/128.0f), &s, &c);
        g_TwC[idx] = make_float2(c, s);
    }
    if (idx < 32*256) { // Ct/St
        int kw = idx >> 8, w = idx & 255;
        sincospif((float)((kw*w)&255) * (1.0f/128.0f), &s, &c);
        float coef = ((kw == 0) ? 1.0f : 2.0f) * (1.0f/65536.0f);
        g_Ct[idx] = coef * c;
        g_St[idx] = -coef * s;
    }
}

// ----------------------------- repacks -------------------------------------
__global__ void k_repack_wp(const float* __restrict__ w1r, const float* __restrict__ w1i,
                            const float* __restrict__ w2r, const float* __restrict__ w2i) {
    int idx = blockIdx.x * 256 + threadIdx.x;
    if (idx >= 2048*4096) return;
    int co  = idx & 63;
    int ci  = (idx >> 6) & 63;
    int kw  = (idx >> 12) & 31;
    int khi = idx >> 17;
    int kx  = (khi < 32) ? khi : khi - 32;
    int s   = ((ci*64 + co)*32 + kx)*32 + kw;
    g_Wp[idx] = (khi < 32) ? make_float2(w1r[s], w1i[s]) : make_float2(w2r[s], w2i[s]);
}

__global__ void k_repack_wc(const float* __restrict__ wc) {
    int idx = blockIdx.x * 256 + threadIdx.x;
    if (idx >= 64*9*64) return;
    int co = idx & 63, tap = (idx >> 6) % 9, ci = idx / 576;
    g_Wc[idx] = wc[(co*64 + ci)*9 + tap];
}

__global__ void k_repack_mlp(const float* __restrict__ w1, const float* __restrict__ w2) {
    int idx = blockIdx.x * 256 + threadIdx.x;
    if (idx < 8192) { // W1t[ci][hid] = w1[hid][ci]
        int ci = idx >> 7, hid = idx & 127;
        g_W1t[idx] = w1[hid*64 + ci];
    }
    if (idx < 8192) { // W2t[hid][co] = w2[co][hid]
        int hid = idx >> 6, co = idx & 63;
        g_W2t[idx] = w2[co*128 + hid];
    }
}

// ------------------ stage A: fwd DFT over W (32 bins) -----------------------
__global__ __launch_bounds__(256) void k_stageA(const float* __restrict__ x) {
    __shared__ float xs[32*256]; // 32 h rows
    int bc = blockIdx.x >> 3, hblk = blockIdx.x & 7;
    int t = threadIdx.x;
    for (int i = t; i < 32*256; i += 256) {
        int h = i >> 8, w = i & 255;
        xs[i] = x[(size_t)bc*65536 + (size_t)(hblk*32 + h)*256 + w];
    }
    __syncthreads();
    int kw = t & 31, h0 = (t >> 5) * 4;
    float ar[4] = {0,0,0,0}, ai[4] = {0,0,0,0};
    for (int w = 0; w < 256; w++) {
        float2 tw = g_TwA[w*32 + kw];
        #pragma unroll
        for (int i = 0; i < 4; i++) {
            float xv = xs[(h0+i)*256 + w];
            ar[i] += xv * tw.x;
            ai[i] += xv * tw.y;
        }
    }
    #pragma unroll
    for (int i = 0; i < 4; i++)
        g_Y1[((size_t)bc*256 + hblk*32 + h0 + i)*32 + kw] = make_float2(ar[i], ai[i]);
}

// ------------------ stage B: fwd DFT over H (64 bins) -----------------------
__global__ __launch_bounds__(256) void k_stageB() {
    __shared__ __align__(16) float2 ys[256*16];
    int bc = blockIdx.x >> 1, kh2 = blockIdx.x & 1;
    int t = threadIdx.x;
    for (int i = t; i < 4096; i += 256) {
        int h = i >> 4, kwl = i & 15;
        ys[i] = g_Y1[(size_t)bc*8192 + h*32 + kh2*16 + kwl];
    }
    __syncthreads();
    int kwl = t & 15, khi0 = (t >> 4) * 4;
    float yr[4] = {0,0,0,0}, yi[4] = {0,0,0,0};
    for (int h = 0; h < 256; h++) {
        float2 y = ys[h*16 + kwl];
        const float4* tb = (const float4*)(g_TwB + h*64 + khi0);
        float4 t0 = tb[0], t1 = tb[1];
        yr[0] += y.x*t0.x - y.y*t0.y;  yi[0] += y.x*t0.y + y.y*t0.x;
        yr[1] += y.x*t0.z - y.y*t0.w;  yi[1] += y.x*t0.w + y.y*t0.z;
        yr[2] += y.x*t1.x - y.y*t1.y;  yi[2] += y.x*t1.y + y.y*t1.x;
        yr[3] += y.x*t1.z - y.y*t1.w;  yi[3] += y.x*t1.w + y.y*t1.z;
    }
    #pragma unroll
    for (int j = 0; j < 4; j++)
        g_Y2[(size_t)bc*2048 + (khi0+j)*32 + kh2*16 + kwl] = make_float2(yr[j], yi[j]);
}

// ------------------ stage C: per-mode channel mix ---------------------------
__global__ __launch_bounds__(256) void k_stageC() {
    __shared__ __align__(16) float2 ysm[512];   // [b][ci]
    __shared__ __align__(16) float2 ws[4096];   // [ci][co]
    int mode = blockIdx.x, t = threadIdx.x;
    for (int i = t; i < 512; i += 256) {
        int b = i >> 6, ci = i & 63;
        ysm[i] = g_Y2[(size_t)(b*64 + ci)*2048 + mode];
    }
    const float4* src = (const float4*)(g_Wp + (size_t)mode*4096);
    float4* dst = (float4*)ws;
    for (int i = t; i < 2048; i += 256) dst[i] = src[i];
    __syncthreads();
    int co = t & 63, bg = t >> 6;
    float ar = 0, ai = 0, br = 0, bi = 0;
    for (int ci = 0; ci < 64; ci++) {
        float2 w = ws[ci*64 + co];
        float2 ya = ysm[bg*64 + ci];
        float2 yb = ysm[(bg+4)*64 + ci];
        ar += ya.x*w.x - ya.y*w.y;  ai += ya.x*w.y + ya.y*w.x;
        br += yb.x*w.x - yb.y*w.y;  bi += yb.x*w.y + yb.y*w.x;
    }
    g_Z[(size_t)(bg*64 + co)*2048 + mode]     = make_float2(ar, ai);
    g_Z[(size_t)((bg+4)*64 + co)*2048 + mode] = make_float2(br, bi);
}

// ------------------ stage D: inv DFT over H ---------------------------------
__global__ __launch_bounds__(256) void k_stageD() {
    __shared__ __align__(16) float2 zs[64*32];
    int bco = blockIdx.x >> 3, hblk = blockIdx.x & 7;
    int t = threadIdx.x;
    for (int i = t; i < 2048; i += 256) zs[i] = g_Z[(size_t)bco*2048 + i];
    __syncthreads();
    int kw = t & 31, h0 = hblk*32 + (t >> 5)*4;
    float gr[4] = {0,0,0,0}, gi[4] = {0,0,0,0};
    for (int khi = 0; khi < 64; khi++) {
        float2 z = zs[khi*32 + kw];
        const float4* tc = (const float4*)(g_TwC + khi*256 + h0);
        float4 t0 = tc[0], t1 = tc[1];
        gr[0] += z.x*t0.x - z.y*t0.y;  gi[0] += z.x*t0.y + z.y*t0.x;
        gr[1] += z.x*t0.z - z.y*t0.w;  gi[1] += z.x*t0.w + z.y*t0.z;
        gr[2] += z.x*t1.x - z.y*t1.y;  gi[2] += z.x*t1.y + z.y*t1.x;
        gr[3] += z.x*t1.z - z.y*t1.w;  gi[3] += z.x*t1.w + z.y*t1.z;
    }
    #pragma unroll
    for (int i = 0; i < 4; i++)
        g_G[(size_t)bco*8192 + (h0+i)*32 + kw] = make_float2(gr[i], gi[i]);
}

// ------------------ stage E: inv DFT over W + add to out --------------------
__global__ __launch_bounds__(256) void k_stageE(float* __restrict__ out) {
    __shared__ __align__(16) float2 gt[32*33];  // [kw][h] padded
    __shared__ __align__(16) float  Cs[32*64];
    __shared__ __align__(16) float  Ss[32*64];
    __shared__ __align__(16) float  st[32*65];  // [h][w] padded
    int bco = blockIdx.x >> 5, hblk = (blockIdx.x >> 2) & 7, wblk = blockIdx.x & 3;
    int t = threadIdx.x;
    for (int i = t; i < 1024; i += 256) {
        int h = i >> 5, kw = i & 31;
        gt[kw*33 + h] = g_G[(size_t)bco*8192 + (hblk*32 + h)*32 + kw];
    }
    for (int i = t; i < 2048; i += 256) {
        int kw = i >> 6, wl = i & 63;
        Cs[i] = g_Ct[kw*256 + wblk*64 + wl];
        Ss[i] = g_St[kw*256 + wblk*64 + wl];
    }
    __syncthreads();
    int h = t & 31, wg = t >> 5;
    float acc[8] = {0,0,0,0,0,0,0,0};
    for (int kw = 0; kw < 32; kw++) {
        float2 g = gt[kw*33 + h];
        const float4* c4 = (const float4*)(Cs + kw*64 + wg*8);
        const float4* s4 = (const float4*)(Ss + kw*64 + wg*8);
        float4 c0 = c4[0], c1 = c4[1], s0 = s4[0], s1 = s4[1];
        acc[0] += g.x*c0.x + g.y*s0.x;  acc[1] += g.x*c0.y + g.y*s0.y;
        acc[2] += g.x*c0.z + g.y*s0.z;  acc[3] += g.x*c0.w + g.y*s0.w;
        acc[4] += g.x*c1.x + g.y*s1.x;  acc[5] += g.x*c1.y + g.y*s1.y;
        acc[6] += g.x*c1.z + g.y*s1.z;  acc[7] += g.x*c1.w + g.y*s1.w;
    }
    #pragma unroll
    for (int j = 0; j < 8; j++) st[h*65 + wg*8 + j] = acc[j];
    __syncthreads();
    for (int i = t; i < 2048; i += 256) {
        int h2 = i >> 6, wl = i & 63;
        size_t o = (size_t)bco*65536 + (size_t)(hblk*32 + h2)*256 + wblk*64 + wl;
        out[o] += st[h2*65 + wl];
    }
}

// ------------------ MLP: 64 -> 128 gelu -> 64 (writes out) ------------------
__global__ __launch_bounds__(256) void k_mlp(const float* __restrict__ x,
                                             const float* __restrict__ b1,
                                             const float* __restrict__ b2,
                                             float* __restrict__ out) {
    __shared__ __align__(16) float xs[64*64];   // [ci][px]
    __shared__ __align__(16) float hs[128*64];  // [hid][px]
    int b = blockIdx.x >> 10;
    int hw0 = (blockIdx.x & 1023) * 64;
    int t = threadIdx.x;
    for (int i = t; i < 4096; i += 256) {
        int ci = i >> 6, px = i & 63;
        xs[i] = x[(size_t)(b*64 + ci)*65536 + hw0 + px];
    }
    __syncthreads();
    // phase 1
    {
        int px = t & 63, half = t >> 6;   // half in 0..3, 32 hid each
        float acc[32];
        const float4* bb = (const float4*)(b1 + half*32);
        #pragma unroll
        for (int j = 0; j < 8; j++) {
            float4 v = bb[j];
            acc[j*4+0] = v.x; acc[j*4+1] = v.y; acc[j*4+2] = v.z; acc[j*4+3] = v.w;
        }
        for (int ci = 0; ci < 64; ci++) {
            float xv = xs[ci*64 + px];
            const float4* w4 = (const float4*)(g_W1t + ci*128 + half*32);
            #pragma unroll
            for (int j = 0; j < 8; j++) {
                float4 w = w4[j];
                acc[j*4+0] += xv*w.x; acc[j*4+1] += xv*w.y;
                acc[j*4+2] += xv*w.z; acc[j*4+3] += xv*w.w;
            }
        }
        #pragma unroll
        for (int j = 0; j < 32; j++) {
            float a = acc[j];
            float g = 0.5f * a * (1.0f + erff(a * 0.70710678118654752f));
            hs[(half*32 + j)*64 + px] = g;
        }
    }
    __syncthreads();
    // phase 2
    {
        int px = t & 63, cog = t >> 6;  // 16 co each
        float acc[16];
        const float4* bb = (const float4*)(b2 + cog*16);
        #pragma unroll
        for (int j = 0; j < 4; j++) {
            float4 v = bb[j];
            acc[j*4+0] = v.x; acc[j*4+1] = v.y; acc[j*4+2] = v.z; acc[j*4+3] = v.w;
        }
        for (int hid = 0; hid < 128; hid++) {
            float hv = hs[hid*64 + px];
            const float4* w4 = (const float4*)(g_W2t + hid*64 + cog*16);
            #pragma unroll
            for (int j = 0; j < 4; j++) {
                float4 w = w4[j];
                acc[j*4+0] += hv*w.x; acc[j*4+1] += hv*w.y;
                acc[j*4+2] += hv*w.z; acc[j*4+3] += hv*w.w;
            }
        }
        #pragma unroll
        for (int j = 0; j < 16; j++) {
            int co = cog*16 + j;
            out[(size_t)(b*64 + co)*65536 + hw0 + px] = acc[j];
        }
    }
}

// ------------------ Conv3x3 (adds into out) ---------------------------------
__global__ __launch_bounds__(256) void k_conv(const float* __restrict__ x,
                                              const float* __restrict__ bconv,
                                              float* __restrict__ out) {
    __shared__ __align__(16) float xt[18*20];
    __shared__ __align__(16) float ws[576];
    int b = blockIdx.x >> 8;
    int tile = blockIdx.x & 255;
    int hbase = (tile >> 4) * 16, wbase = (tile & 15) * 16;
    int t = threadIdx.x;
    int py = t >> 4, px = t & 15;
    float acc[64];
    #pragma unroll
    for (int j = 0; j < 64; j++) acc[j] = 0.0f;

    for (int ci = 0; ci < 64; ci++) {
        __syncthreads();
        for (int i = t; i < 324; i += 256) {
            int ih = i / 18, iw = i % 18;
            int gh = hbase + ih - 1, gw = wbase + iw - 1;
            float v = 0.0f;
            if (gh >= 0 && gh < 256 && gw >= 0 && gw < 256)
                v = x[(size_t)(b*64 + ci)*65536 + (size_t)gh*256 + gw];
            xt[ih*20 + iw] = v;
        }
        for (int i = t; i < 576; i += 256) ws[i] = g_Wc[ci*576 + i];
        __syncthreads();
        #pragma unroll
        for (int tap = 0; tap < 9; tap++) {
            int dy = tap / 3, dx = tap % 3;
            float xv = xt[(py+dy)*20 + px + dx];
            const float4* w4 = (const float4*)(ws + tap*64);
            #pragma unroll
            for (int j = 0; j < 16; j++) {
                float4 w = w4[j];
                acc[j*4+0] += xv*w.x; acc[j*4+1] += xv*w.y;
                acc[j*4+2] += xv*w.z; acc[j*4+3] += xv*w.w;
            }
        }
    }
    size_t base = (size_t)b*64*65536 + (size_t)(hbase + py)*256 + wbase + px;
    #pragma unroll
    for (int j = 0; j < 64; j++)
        out[base + (size_t)j*65536] += acc[j] + __ldg(&bconv[j]);
}

// ------------------------------- launcher -----------------------------------
extern "C" void kernel_launch(void* const* d_in, const int* in_sizes, int n_in,
                              void* d_out, int out_size) {
    const float* x      = (const float*)d_in[0];
    const float* w1r    = (const float*)d_in[1];
    const float* w1i    = (const float*)d_in[2];
    const float* w2r    = (const float*)d_in[3];
    const float* w2i    = (const float*)d_in[4];
    const float* w_mlp1 = (const float*)d_in[5];
    const float* b_mlp1 = (const float*)d_in[6];
    const float* w_mlp2 = (const float*)d_in[7];
    const float* b_mlp2 = (const float*)d_in[8];
    const float* w_conv = (const float*)d_in[9];
    const float* b_conv = (const float*)d_in[10];
    float* out = (float*)d_out;

    k_tables<<<64, 256>>>();
    k_repack_wp<<<32768, 256>>>(w1r, w1i, w2r, w2i);
    k_repack_wc<<<144, 256>>>(w_conv);
    k_repack_mlp<<<32, 256>>>(w_mlp1, w_mlp2);

    k_stageA<<<4096, 256>>>(x);
    k_stageB<<<1024, 256>>>();
    k_stageC<<<2048, 256>>>();
    k_stageD<<<4096, 256>>>();

    k_mlp<<<8192, 256>>>(x, b_mlp1, b_mlp2, out);
    k_conv<<<2048, 256>>>(x, b_conv, out);
    k_stageE<<<16384, 256>>>(out);
}